// round 7
// baseline (speedup 1.0000x reference)
#include <cuda_runtime.h>
#include <cuda_bf16.h>
#include <cstdint>

#define B_ 8
#define T_ 256
#define H_ 1024
#define V_ 32000
#define M_ (B_*T_)          // 2048 rows = (b,t)

// ---------------- scratch (device globals; no allocation allowed) ----------
__device__ __align__(16) __nv_bfloat16 g_Ahi[M_*H_];           // emb hi
__device__ __align__(16) __nv_bfloat16 g_Alo[M_*H_];           // emb lo
__device__ __align__(16) __nv_bfloat16 g_Wih_hi[H_*H_];
__device__ __align__(16) __nv_bfloat16 g_Wih_lo[H_*H_];
__device__ __align__(16) __nv_bfloat16 g_Wo_hi[(size_t)V_*H_];
__device__ __align__(16) __nv_bfloat16 g_Wo_lo[(size_t)V_*H_];
__device__ __align__(16) __nv_bfloat16 g_Hhi[M_*H_];           // hs hi
__device__ __align__(16) __nv_bfloat16 g_Hlo[M_*H_];           // hs lo
__device__ __align__(16) float g_pre[M_*H_];   // x_t @ W_ih^T + b_ih + b_hh
__device__ __align__(16) float g_hs [M_*H_];   // hidden states [b][t][j]
__device__ __align__(16) float g_h  [2*B_*H_]; // double-buffered current h
__device__ float g_bsum[H_];
__device__ unsigned g_bar_count;
__device__ unsigned g_bar_gen;

// ---------------- PTX helpers (arch-neutral: ldmatrix/mma/cp.async) --------
__device__ __forceinline__ uint32_t smem_to_u32(const void* p) {
    uint32_t a;
    asm("{ .reg .u64 t; cvta.to.shared.u64 t, %1; cvt.u32.u64 %0, t; }"
        : "=r"(a) : "l"(p));
    return a;
}
__device__ __forceinline__ void ldsm_x4(uint32_t* r, uint32_t addr) {
    asm volatile("ldmatrix.sync.aligned.m8n8.x4.shared.b16 {%0,%1,%2,%3}, [%4];"
        : "=r"(r[0]), "=r"(r[1]), "=r"(r[2]), "=r"(r[3]) : "r"(addr));
}
__device__ __forceinline__ void mma_bf16(float* d, const uint32_t* a, const uint32_t* b) {
    asm volatile(
        "mma.sync.aligned.m16n8k16.row.col.f32.bf16.bf16.f32 "
        "{%0,%1,%2,%3}, {%4,%5,%6,%7}, {%8,%9}, {%0,%1,%2,%3};"
        : "+f"(d[0]), "+f"(d[1]), "+f"(d[2]), "+f"(d[3])
        : "r"(a[0]), "r"(a[1]), "r"(a[2]), "r"(a[3]), "r"(b[0]), "r"(b[1]));
}
__device__ __forceinline__ void cp16(uint32_t saddr, const void* g) {
    asm volatile("cp.async.cg.shared.global [%0], [%1], 16;" :: "r"(saddr), "l"(g));
}
#define CP_COMMIT() asm volatile("cp.async.commit_group;" ::: "memory")
#define CP_WAIT0()  asm volatile("cp.async.wait_group 0;" ::: "memory")
#define CP_WAIT1()  asm volatile("cp.async.wait_group 1;" ::: "memory")

// ---------------- gather: emb rows split to bf16 hi/lo + fused bias --------
__global__ void gather_kernel(const int* __restrict__ x,
                              const float* __restrict__ embed,
                              const float* __restrict__ b_ih,
                              const float* __restrict__ b_hh) {
    int m = blockIdx.x;
    if (m < M_) {
        int tok = x[m];
        for (int i = threadIdx.x; i < H_; i += blockDim.x) {
            float v = embed[(size_t)tok * H_ + i];
            __nv_bfloat16 h = __float2bfloat16(v);
            g_Ahi[(size_t)m * H_ + i] = h;
            g_Alo[(size_t)m * H_ + i] = __float2bfloat16(v - __bfloat162float(h));
        }
    } else {
        for (int i = threadIdx.x; i < H_; i += blockDim.x)
            g_bsum[i] = b_ih[i] + b_hh[i];
    }
}

// ---------------- fp32 -> bf16 hi/lo split ---------------------------------
__global__ void split_kernel(const float* __restrict__ src,
                             __nv_bfloat16* __restrict__ hi,
                             __nv_bfloat16* __restrict__ lo, size_t n) {
    size_t i = ((size_t)blockIdx.x * blockDim.x + threadIdx.x) * 4;
    if (i < n) {
        float4 v = *reinterpret_cast<const float4*>(src + i);
        __nv_bfloat16 h0 = __float2bfloat16(v.x), h1 = __float2bfloat16(v.y);
        __nv_bfloat16 h2 = __float2bfloat16(v.z), h3 = __float2bfloat16(v.w);
        __nv_bfloat162 hh0 = {h0, h1}, hh1 = {h2, h3};
        __nv_bfloat162 ll0 = {__float2bfloat16(v.x - __bfloat162float(h0)),
                              __float2bfloat16(v.y - __bfloat162float(h1))};
        __nv_bfloat162 ll1 = {__float2bfloat16(v.z - __bfloat162float(h2)),
                              __float2bfloat16(v.w - __bfloat162float(h3))};
        *reinterpret_cast<__nv_bfloat162*>(hi + i)     = hh0;
        *reinterpret_cast<__nv_bfloat162*>(hi + i + 2) = hh1;
        *reinterpret_cast<__nv_bfloat162*>(lo + i)     = ll0;
        *reinterpret_cast<__nv_bfloat162*>(lo + i + 2) = ll1;
    }
}

// ---------------- split-bf16 HMMA GEMM (3-stage, swizzled, 1 sync/chunk) ---
// C[r][c] = sum_k A[r][k]*B[c][k] + bias[c] via Ahi*Bhi + Ahi*Blo + Alo*Bhi.
// A: [Mrows][H_] row-major, B: [Ncols][H_] row-major.  K = H_ = 1024 fixed.
// smem layout per matrix tile: 128 rows x 32 bf16 (64B/row), XOR-swizzled:
//   byte_off(r, seg) = r*64 + (seg ^ ((r>>1)&3))*16     (seg = 16B unit, 0..3)
// -> every ldmatrix 8-row phase hits 8 distinct 16B quads (conflict-free).
#define GBM 128
#define GBN 128
#define GBK 32
#define NKC (H_/GBK)                    // 32 k-chunks
#define MAT_B (GBM*GBK*2)               // 8192 bytes per matrix tile
#define STAGE_B (4*MAT_B)               // 32768 bytes per stage
#define NSTAGE 3
#define SMEM_B (NSTAGE*STAGE_B)         // 98304 bytes total

__device__ __forceinline__ uint32_t swz(int row, int seg) {
    return (uint32_t)(row*64 + ((seg ^ ((row >> 1) & 3)) << 4));
}

__global__ __launch_bounds__(256, 2)
void gemm_mma(const __nv_bfloat16* __restrict__ Ahi, const __nv_bfloat16* __restrict__ Alo,
              const __nv_bfloat16* __restrict__ Bhi, const __nv_bfloat16* __restrict__ Blo,
              const float* __restrict__ bias, float* __restrict__ C, int Ndim) {
    extern __shared__ __align__(16) char sm[];
    const uint32_t sb = smem_to_u32(sm);
    const int tid  = threadIdx.x;
    const int lane = tid & 31, wid = tid >> 5;
    const int wm = wid & 3, wn = wid >> 2;      // warp tile: rows 32*wm, cols 64*wn
    const int bm = blockIdx.x, bn = blockIdx.y;

    // ---- prefetch chunk c into stage c%3 (8 x cp.async.16B per thread) ----
    auto prefetch = [&](int c) {
        const uint32_t st = sb + (uint32_t)(c % NSTAGE) * STAGE_B;
        const int kcol = c * GBK;
        #pragma unroll
        for (int q = 0; q < 2; q++) {
            const int u = tid + 256*q;
            const int r = u >> 2, sg = u & 3;
            const uint32_t so = swz(r, sg);
            const size_t goA = (size_t)(bm*GBM + r) * H_ + kcol + sg*8;
            const size_t goB = (size_t)(bn*GBN + r) * H_ + kcol + sg*8;
            cp16(st + 0*MAT_B + so, Ahi + goA);
            cp16(st + 1*MAT_B + so, Alo + goA);
            cp16(st + 2*MAT_B + so, Bhi + goB);
            cp16(st + 3*MAT_B + so, Blo + goB);
        }
    };

    float acc[2][8][4];
    #pragma unroll
    for (int i = 0; i < 2; i++)
        #pragma unroll
        for (int j = 0; j < 8; j++)
            #pragma unroll
            for (int q = 0; q < 4; q++) acc[i][j][q] = 0.f;

    prefetch(0); CP_COMMIT();
    prefetch(1); CP_COMMIT();

    for (int c = 0; c < NKC; c++) {
        if (c + 1 < NKC) CP_WAIT1();     // chunk c landed (c+1 may still fly)
        else             CP_WAIT0();
        __syncthreads();                  // visibility + guards stage reuse
        if (c + 2 < NKC) { prefetch(c + 2); CP_COMMIT(); }

        const uint32_t st = sb + (uint32_t)(c % NSTAGE) * STAGE_B;
        #pragma unroll
        for (int ks = 0; ks < 2; ks++) {
            // A fragments (hi & lo): rows wm*32 + f*16 + lane%16
            uint32_t ah[8], al[8];
            #pragma unroll
            for (int f = 0; f < 2; f++) {
                const int row = wm*32 + f*16 + (lane & 15);
                const uint32_t off = swz(row, ks*2 + (lane >> 4));
                ldsm_x4(ah + 4*f, st + 0*MAT_B + off);
                ldsm_x4(al + 4*f, st + 1*MAT_B + off);
            }
            // B fragments per 16-col group; MMAs issued immediately after.
            #pragma unroll
            for (int p = 0; p < 4; p++) {
                uint32_t bh4[4], bl4[4];
                const int n = wn*64 + p*16 + ((lane >> 4) << 3) + (lane & 7);
                const uint32_t off = swz(n, ks*2 + ((lane >> 3) & 1));
                ldsm_x4(bh4, st + 2*MAT_B + off);
                ldsm_x4(bl4, st + 3*MAT_B + off);
                #pragma unroll
                for (int fm = 0; fm < 2; fm++)
                    #pragma unroll
                    for (int q = 0; q < 2; q++) {
                        float* a4 = acc[fm][2*p + q];
                        mma_bf16(a4, ah + 4*fm, bh4 + 2*q);
                        mma_bf16(a4, ah + 4*fm, bl4 + 2*q);
                        mma_bf16(a4, al + 4*fm, bh4 + 2*q);
                    }
            }
        }
    }

    // ---- epilogue: acc + bias -> C ----
    #pragma unroll
    for (int fm = 0; fm < 2; fm++) {
        const int row = bm*GBM + wm*32 + fm*16 + (lane >> 2);
        #pragma unroll
        for (int fn = 0; fn < 8; fn++) {
            const int col = bn*GBN + wn*64 + fn*8 + (lane & 3)*2;
            const float2 bv = *reinterpret_cast<const float2*>(bias + col);
            float2 o0, o1;
            o0.x = acc[fm][fn][0] + bv.x; o0.y = acc[fm][fn][1] + bv.y;
            o1.x = acc[fm][fn][2] + bv.x; o1.y = acc[fm][fn][3] + bv.y;
            *reinterpret_cast<float2*>(C + (size_t)row     * Ndim + col) = o0;
            *reinterpret_cast<float2*>(C + (size_t)(row+8) * Ndim + col) = o1;
        }
    }
}

// ---------------- persistent scan kernel (unchanged, passing) --------------
#define SCAN_BLOCKS 128

__device__ __forceinline__ void grid_barrier(int nb) {
    __syncthreads();
    if (threadIdx.x == 0) {
        unsigned g = *((volatile unsigned*)&g_bar_gen);
        __threadfence();
        if (atomicAdd(&g_bar_count, 1) == (unsigned)(nb - 1)) {
            g_bar_count = 0;
            __threadfence();
            *((volatile unsigned*)&g_bar_gen) = g + 1;
        } else {
            while (*((volatile unsigned*)&g_bar_gen) == g) { __nanosleep(32); }
        }
        __threadfence();
    }
    __syncthreads();
}

__global__ __launch_bounds__(256)
void scan_kernel(const float* __restrict__ Whh, float* __restrict__ hfinal) {
    __shared__ __align__(16) float hsh[B_*H_];
    const int tid  = threadIdx.x;
    const int warp = tid >> 5;
    const int lane = tid & 31;
    const int j    = blockIdx.x * 8 + warp;

    float4 w[8];
    const float4* wrow = reinterpret_cast<const float4*>(Whh + (size_t)j * H_);
    #pragma unroll
    for (int i = 0; i < 8; i++) w[i] = wrow[lane + 32*i];

    for (int idx = blockIdx.x*256 + tid; idx < B_*H_; idx += SCAN_BLOCKS*256)
        g_h[idx] = 0.f;
    grid_barrier(SCAN_BLOCKS);

    for (int t = 0; t < T_; t++) {
        const int rp = t & 1, wp = rp ^ 1;
        float4* hs4 = reinterpret_cast<float4*>(hsh);
        const float4* hg4 = reinterpret_cast<const float4*>(g_h + rp*B_*H_);
        #pragma unroll
        for (int i = 0; i < (B_*H_/4)/256; i++) hs4[tid + 256*i] = hg4[tid + 256*i];
        __syncthreads();

        float acc[B_];
        #pragma unroll
        for (int b = 0; b < B_; b++) acc[b] = 0.f;
        #pragma unroll
        for (int i = 0; i < 8; i++) {
            const float4 wv = w[i];
            #pragma unroll
            for (int b = 0; b < B_; b++) {
                const float4 hv = *reinterpret_cast<const float4*>(&hsh[b*H_ + lane*4 + 128*i]);
                acc[b] += wv.x*hv.x + wv.y*hv.y + wv.z*hv.z + wv.w*hv.w;
            }
        }
        #pragma unroll
        for (int b = 0; b < B_; b++) {
            #pragma unroll
            for (int off = 16; off; off >>= 1)
                acc[b] += __shfl_xor_sync(0xffffffffu, acc[b], off);
        }
        if (lane < B_) {
            float a = acc[0];
            if (lane == 1) a = acc[1];
            if (lane == 2) a = acc[2];
            if (lane == 3) a = acc[3];
            if (lane == 4) a = acc[4];
            if (lane == 5) a = acc[5];
            if (lane == 6) a = acc[6];
            if (lane == 7) a = acc[7];
            const float hn = tanhf(a + g_pre[(size_t)lane*(T_*H_) + t*H_ + j]);
            g_h[wp*B_*H_ + lane*H_ + j] = hn;
            g_hs[(size_t)lane*(T_*H_) + t*H_ + j] = hn;
            if (t == T_-1) hfinal[lane*H_ + j] = hn;
        }
        __threadfence();
        grid_barrier(SCAN_BLOCKS);
    }
}

// ---------------- launch ----------------------------------------------------
extern "C" void kernel_launch(void* const* d_in, const int* in_sizes, int n_in,
                              void* d_out, int out_size) {
    const int*   x     = (const int*)  d_in[0];
    const float* embed = (const float*)d_in[1];
    const float* W_ih  = (const float*)d_in[2];
    const float* b_ih  = (const float*)d_in[3];
    const float* W_hh  = (const float*)d_in[4];
    const float* b_hh  = (const float*)d_in[5];
    const float* W_out = (const float*)d_in[6];
    const float* b_out = (const float*)d_in[7];
    float* out = (float*)d_out;

    void *p_Ahi, *p_Alo, *p_Wih_hi, *p_Wih_lo, *p_Wo_hi, *p_Wo_lo;
    void *p_Hhi, *p_Hlo, *p_pre, *p_hs, *p_bsum;
    cudaGetSymbolAddress(&p_Ahi, g_Ahi);       cudaGetSymbolAddress(&p_Alo, g_Alo);
    cudaGetSymbolAddress(&p_Wih_hi, g_Wih_hi); cudaGetSymbolAddress(&p_Wih_lo, g_Wih_lo);
    cudaGetSymbolAddress(&p_Wo_hi, g_Wo_hi);   cudaGetSymbolAddress(&p_Wo_lo, g_Wo_lo);
    cudaGetSymbolAddress(&p_Hhi, g_Hhi);       cudaGetSymbolAddress(&p_Hlo, g_Hlo);
    cudaGetSymbolAddress(&p_pre, g_pre);       cudaGetSymbolAddress(&p_hs, g_hs);
    cudaGetSymbolAddress(&p_bsum, g_bsum);

    cudaFuncSetAttribute(gemm_mma, cudaFuncAttributeMaxDynamicSharedMemorySize, SMEM_B);

    // 1) gather embeddings (split to bf16 hi/lo) + fused bias
    gather_kernel<<<M_ + 1, 256>>>(x, embed, b_ih, b_hh);

    // 2) split weights to bf16 hi/lo
    split_kernel<<<(H_*H_/4 + 255)/256, 256>>>(W_ih,
        (__nv_bfloat16*)p_Wih_hi, (__nv_bfloat16*)p_Wih_lo, (size_t)H_*H_);
    split_kernel<<<(int)(((size_t)V_*H_/4 + 255)/256), 256>>>(W_out,
        (__nv_bfloat16*)p_Wo_hi, (__nv_bfloat16*)p_Wo_lo, (size_t)V_*H_);

    // 3) pre = emb @ W_ih^T + (b_ih + b_hh)   [2048 x 1024]
    gemm_mma<<<dim3(M_/GBM, H_/GBN), 256, SMEM_B>>>(
        (const __nv_bfloat16*)p_Ahi, (const __nv_bfloat16*)p_Alo,
        (const __nv_bfloat16*)p_Wih_hi, (const __nv_bfloat16*)p_Wih_lo,
        (const float*)p_bsum, (float*)p_pre, H_);

    // 4) persistent recurrent scan; writes g_hs and h_final tail of d_out
    scan_kernel<<<SCAN_BLOCKS, 256>>>(W_hh, out + (size_t)M_ * V_);

    // 5) split hidden states to bf16 hi/lo
    split_kernel<<<(M_*H_/4 + 255)/256, 256>>>((const float*)p_hs,
        (__nv_bfloat16*)p_Hhi, (__nv_bfloat16*)p_Hlo, (size_t)M_*H_);

    // 6) outputs = hs @ W_out^T + b_out   [2048 x 32000]
    gemm_mma<<<dim3(M_/GBM, V_/GBN), 256, SMEM_B>>>(
        (const __nv_bfloat16*)p_Hhi, (const __nv_bfloat16*)p_Hlo,
        (const __nv_bfloat16*)p_Wo_hi, (const __nv_bfloat16*)p_Wo_lo,
        b_out, out, V_);
}

// round 8
// speedup vs baseline: 1.3745x; 1.3745x over previous
#include <cuda_runtime.h>
#include <cuda_bf16.h>
#include <cstdint>

#define B_ 8
#define T_ 256
#define H_ 1024
#define V_ 32000
#define M_ (B_*T_)          // 2048 rows = (b,t)

// ---------------- scratch (device globals; no allocation allowed) ----------
__device__ __align__(16) __nv_bfloat16 g_Ahi[M_*H_];           // emb hi
__device__ __align__(16) __nv_bfloat16 g_Alo[M_*H_];           // emb lo
__device__ __align__(16) __nv_bfloat16 g_Wih_hi[H_*H_];
__device__ __align__(16) __nv_bfloat16 g_Wih_lo[H_*H_];
__device__ __align__(16) __nv_bfloat16 g_Wo_hi[(size_t)V_*H_];
__device__ __align__(16) __nv_bfloat16 g_Wo_lo[(size_t)V_*H_];
__device__ __align__(16) __nv_bfloat16 g_Hhi[M_*H_];           // hs hi
__device__ __align__(16) __nv_bfloat16 g_Hlo[M_*H_];           // hs lo
__device__ __align__(16) float g_pre[M_*H_];   // x_t @ W_ih^T + b_ih + b_hh
__device__ __align__(16) float g_hs [M_*H_];   // hidden states [b][t][j]
__device__ __align__(16) float g_h  [2*B_*H_]; // double-buffered current h
__device__ float g_bsum[H_];
__device__ unsigned g_bar_count;
__device__ unsigned g_bar_gen;

// ---------------- PTX helpers (arch-neutral: ldmatrix/mma/cp.async) --------
__device__ __forceinline__ uint32_t smem_to_u32(const void* p) {
    uint32_t a;
    asm("{ .reg .u64 t; cvta.to.shared.u64 t, %1; cvt.u32.u64 %0, t; }"
        : "=r"(a) : "l"(p));
    return a;
}
__device__ __forceinline__ void ldsm_x4(uint32_t* r, uint32_t addr) {
    asm volatile("ldmatrix.sync.aligned.m8n8.x4.shared.b16 {%0,%1,%2,%3}, [%4];"
        : "=r"(r[0]), "=r"(r[1]), "=r"(r[2]), "=r"(r[3]) : "r"(addr));
}
__device__ __forceinline__ void mma_bf16(float* d, const uint32_t* a, const uint32_t* b) {
    asm volatile(
        "mma.sync.aligned.m16n8k16.row.col.f32.bf16.bf16.f32 "
        "{%0,%1,%2,%3}, {%4,%5,%6,%7}, {%8,%9}, {%0,%1,%2,%3};"
        : "+f"(d[0]), "+f"(d[1]), "+f"(d[2]), "+f"(d[3])
        : "r"(a[0]), "r"(a[1]), "r"(a[2]), "r"(a[3]), "r"(b[0]), "r"(b[1]));
}
__device__ __forceinline__ void cp16(uint32_t saddr, const void* g) {
    asm volatile("cp.async.cg.shared.global [%0], [%1], 16;" :: "r"(saddr), "l"(g));
}
#define CP_COMMIT() asm volatile("cp.async.commit_group;" ::: "memory")
#define CP_WAIT0()  asm volatile("cp.async.wait_group 0;" ::: "memory")
#define CP_WAIT1()  asm volatile("cp.async.wait_group 1;" ::: "memory")

// ---------------- gather: emb rows split to bf16 hi/lo + fused bias --------
__global__ void gather_kernel(const int* __restrict__ x,
                              const float* __restrict__ embed,
                              const float* __restrict__ b_ih,
                              const float* __restrict__ b_hh) {
    int m = blockIdx.x;
    if (m < M_) {
        int tok = x[m];
        for (int i = threadIdx.x; i < H_; i += blockDim.x) {
            float v = embed[(size_t)tok * H_ + i];
            __nv_bfloat16 h = __float2bfloat16(v);
            g_Ahi[(size_t)m * H_ + i] = h;
            g_Alo[(size_t)m * H_ + i] = __float2bfloat16(v - __bfloat162float(h));
        }
    } else {
        for (int i = threadIdx.x; i < H_; i += blockDim.x)
            g_bsum[i] = b_ih[i] + b_hh[i];
    }
}

// ---------------- fp32 -> bf16 hi/lo split ---------------------------------
__global__ void split_kernel(const float* __restrict__ src,
                             __nv_bfloat16* __restrict__ hi,
                             __nv_bfloat16* __restrict__ lo, size_t n) {
    size_t i = ((size_t)blockIdx.x * blockDim.x + threadIdx.x) * 4;
    if (i < n) {
        float4 v = *reinterpret_cast<const float4*>(src + i);
        __nv_bfloat16 h0 = __float2bfloat16(v.x), h1 = __float2bfloat16(v.y);
        __nv_bfloat16 h2 = __float2bfloat16(v.z), h3 = __float2bfloat16(v.w);
        __nv_bfloat162 hh0 = {h0, h1}, hh1 = {h2, h3};
        __nv_bfloat162 ll0 = {__float2bfloat16(v.x - __bfloat162float(h0)),
                              __float2bfloat16(v.y - __bfloat162float(h1))};
        __nv_bfloat162 ll1 = {__float2bfloat16(v.z - __bfloat162float(h2)),
                              __float2bfloat16(v.w - __bfloat162float(h3))};
        *reinterpret_cast<__nv_bfloat162*>(hi + i)     = hh0;
        *reinterpret_cast<__nv_bfloat162*>(hi + i + 2) = hh1;
        *reinterpret_cast<__nv_bfloat162*>(lo + i)     = ll0;
        *reinterpret_cast<__nv_bfloat162*>(lo + i + 2) = ll1;
    }
}

// ---------------- split-bf16 HMMA GEMM (R6 version: 2-stage, LDT=40) -------
// C[r][c] = sum_k A[r][k]*B[c][k] + bias[c] via Ahi*Bhi + Ahi*Blo + Alo*Bhi.
// A: [Mrows][H_] row-major, B: [Ncols][H_] row-major.  K = H_ = 1024 fixed.
#define GBM 128
#define GBN 128
#define GBK 32
#define NKC (H_/GBK)                    // 32 k-chunks
#define LDT 40                          // smem row stride in bf16 (pad 8)
#define MAT_B (GBM*LDT*2)               // 10240 bytes per matrix tile
#define STAGE_B (4*MAT_B)               // 40960 bytes per stage
#define SMEM_B (2*STAGE_B)              // 81920 bytes total

__global__ __launch_bounds__(256, 2)
void gemm_mma(const __nv_bfloat16* __restrict__ Ahi, const __nv_bfloat16* __restrict__ Alo,
              const __nv_bfloat16* __restrict__ Bhi, const __nv_bfloat16* __restrict__ Blo,
              const float* __restrict__ bias, float* __restrict__ C, int Ndim) {
    extern __shared__ __align__(16) char sm[];
    const uint32_t sb = smem_to_u32(sm);
    const int tid  = threadIdx.x;
    const int lane = tid & 31, wid = tid >> 5;
    const int wm = wid & 3, wn = wid >> 2;      // warp tile: rows 32*wm, cols 64*wn
    const int bm = blockIdx.x, bn = blockIdx.y;

    // ---- prefetch chunk c into stage c&1 (8 x cp.async.16B per thread) ----
    auto prefetch = [&](int c) {
        const uint32_t st = sb + (uint32_t)(c & 1) * STAGE_B;
        const int kcol = c * GBK;
        #pragma unroll
        for (int q = 0; q < 2; q++) {
            const int u = tid + 256*q;
            const int r = u >> 2, sg = u & 3;
            const uint32_t so = (uint32_t)(r*LDT + sg*8) * 2;
            const size_t goA = (size_t)(bm*GBM + r) * H_ + kcol + sg*8;
            const size_t goB = (size_t)(bn*GBN + r) * H_ + kcol + sg*8;
            cp16(st + 0*MAT_B + so, Ahi + goA);
            cp16(st + 1*MAT_B + so, Alo + goA);
            cp16(st + 2*MAT_B + so, Bhi + goB);
            cp16(st + 3*MAT_B + so, Blo + goB);
        }
    };

    float acc[2][8][4];
    #pragma unroll
    for (int i = 0; i < 2; i++)
        #pragma unroll
        for (int j = 0; j < 8; j++)
            #pragma unroll
            for (int q = 0; q < 4; q++) acc[i][j][q] = 0.f;

    prefetch(0); CP_COMMIT();

    for (int c = 0; c < NKC; c++) {
        if (c + 1 < NKC) { prefetch(c + 1); CP_COMMIT(); CP_WAIT1(); }
        else             { CP_WAIT0(); }
        __syncthreads();

        const uint32_t st = sb + (uint32_t)(c & 1) * STAGE_B;
        #pragma unroll
        for (int ks = 0; ks < 2; ks++) {
            // A fragments (hi & lo): rows wm*32 + f*16 + lane%16, k seg lane/16
            uint32_t ah[8], al[8];
            #pragma unroll
            for (int f = 0; f < 2; f++) {
                const int row = wm*32 + f*16 + (lane & 15);
                const uint32_t off = (uint32_t)(row*LDT + ks*16 + (lane >> 4)*8) * 2;
                ldsm_x4(ah + 4*f, st + 0*MAT_B + off);
                ldsm_x4(al + 4*f, st + 1*MAT_B + off);
            }
            // B fragments loaded per 16-col group to keep register pressure
            // low (x4 -> two n8 frags), MMAs issued immediately after.
            #pragma unroll
            for (int p = 0; p < 4; p++) {
                uint32_t bh4[4], bl4[4];
                const int n  = wn*64 + p*16 + ((lane >> 4) << 3) + (lane & 7);
                const int kc = ks*16 + ((lane >> 3) & 1) * 8;
                const uint32_t off = (uint32_t)(n*LDT + kc) * 2;
                ldsm_x4(bh4, st + 2*MAT_B + off);
                ldsm_x4(bl4, st + 3*MAT_B + off);
                #pragma unroll
                for (int fm = 0; fm < 2; fm++)
                    #pragma unroll
                    for (int q = 0; q < 2; q++) {
                        float* a4 = acc[fm][2*p + q];
                        mma_bf16(a4, ah + 4*fm, bh4 + 2*q);
                        mma_bf16(a4, ah + 4*fm, bl4 + 2*q);
                        mma_bf16(a4, al + 4*fm, bh4 + 2*q);
                    }
            }
        }
        __syncthreads();
    }

    // ---- epilogue: acc + bias -> C ----
    #pragma unroll
    for (int fm = 0; fm < 2; fm++) {
        const int row = bm*GBM + wm*32 + fm*16 + (lane >> 2);
        #pragma unroll
        for (int fn = 0; fn < 8; fn++) {
            const int col = bn*GBN + wn*64 + fn*8 + (lane & 3)*2;
            const float2 bv = *reinterpret_cast<const float2*>(bias + col);
            float2 o0, o1;
            o0.x = acc[fm][fn][0] + bv.x; o0.y = acc[fm][fn][1] + bv.y;
            o1.x = acc[fm][fn][2] + bv.x; o1.y = acc[fm][fn][3] + bv.y;
            *reinterpret_cast<float2*>(C + (size_t)row     * Ndim + col) = o0;
            *reinterpret_cast<float2*>(C + (size_t)(row+8) * Ndim + col) = o1;
        }
    }
}

// ---------------- persistent scan kernel: 64 CTAs x 512 threads ------------
#define SCAN_BLOCKS 64
#define SCAN_THREADS 512

__device__ __forceinline__ void grid_barrier(int nb) {
    __syncthreads();
    if (threadIdx.x == 0) {
        unsigned g = *((volatile unsigned*)&g_bar_gen);
        __threadfence();
        if (atomicAdd(&g_bar_count, 1) == (unsigned)(nb - 1)) {
            g_bar_count = 0;
            __threadfence();
            *((volatile unsigned*)&g_bar_gen) = g + 1;
        } else {
            while (*((volatile unsigned*)&g_bar_gen) == g) { __nanosleep(32); }
        }
        __threadfence();
    }
    __syncthreads();
}

__global__ __launch_bounds__(SCAN_THREADS, 1)
void scan_kernel(const float* __restrict__ Whh, float* __restrict__ hfinal) {
    __shared__ __align__(16) float hsh[B_*H_];   // 32 KB
    const int tid  = threadIdx.x;
    const int warp = tid >> 5;                   // 0..15
    const int lane = tid & 31;
    const int j    = blockIdx.x * 16 + warp;     // one output column per warp

    // W_hh row j stays in registers for all 256 steps.
    float4 w[8];
    const float4* wrow = reinterpret_cast<const float4*>(Whh + (size_t)j * H_);
    #pragma unroll
    for (int i = 0; i < 8; i++) w[i] = wrow[lane + 32*i];

    // zero h buffer 0
    for (int idx = blockIdx.x*SCAN_THREADS + tid; idx < B_*H_;
         idx += SCAN_BLOCKS*SCAN_THREADS)
        g_h[idx] = 0.f;
    grid_barrier(SCAN_BLOCKS);

    for (int t = 0; t < T_; t++) {
        const int rp = t & 1, wp = rp ^ 1;
        // stage current h into shared
        float4* hs4 = reinterpret_cast<float4*>(hsh);
        const float4* hg4 = reinterpret_cast<const float4*>(g_h + rp*B_*H_);
        #pragma unroll
        for (int i = 0; i < (B_*H_/4)/SCAN_THREADS; i++)
            hs4[tid + SCAN_THREADS*i] = hg4[tid + SCAN_THREADS*i];
        __syncthreads();

        float acc[B_];
        #pragma unroll
        for (int b = 0; b < B_; b++) acc[b] = 0.f;
        #pragma unroll
        for (int i = 0; i < 8; i++) {
            const float4 wv = w[i];
            #pragma unroll
            for (int b = 0; b < B_; b++) {
                const float4 hv = *reinterpret_cast<const float4*>(&hsh[b*H_ + lane*4 + 128*i]);
                acc[b] += wv.x*hv.x + wv.y*hv.y + wv.z*hv.z + wv.w*hv.w;
            }
        }
        #pragma unroll
        for (int b = 0; b < B_; b++) {
            #pragma unroll
            for (int off = 16; off; off >>= 1)
                acc[b] += __shfl_xor_sync(0xffffffffu, acc[b], off);
        }
        if (lane < B_) {
            float a = acc[0];
            if (lane == 1) a = acc[1];
            if (lane == 2) a = acc[2];
            if (lane == 3) a = acc[3];
            if (lane == 4) a = acc[4];
            if (lane == 5) a = acc[5];
            if (lane == 6) a = acc[6];
            if (lane == 7) a = acc[7];
            const float hn = tanhf(a + g_pre[(size_t)lane*(T_*H_) + t*H_ + j]);
            g_h[wp*B_*H_ + lane*H_ + j] = hn;
            g_hs[(size_t)lane*(T_*H_) + t*H_ + j] = hn;
            if (t == T_-1) hfinal[lane*H_ + j] = hn;
            __threadfence();
        }
        grid_barrier(SCAN_BLOCKS);
    }
}

// ---------------- launch ----------------------------------------------------
extern "C" void kernel_launch(void* const* d_in, const int* in_sizes, int n_in,
                              void* d_out, int out_size) {
    const int*   x     = (const int*)  d_in[0];
    const float* embed = (const float*)d_in[1];
    const float* W_ih  = (const float*)d_in[2];
    const float* b_ih  = (const float*)d_in[3];
    const float* W_hh  = (const float*)d_in[4];
    const float* b_hh  = (const float*)d_in[5];
    const float* W_out = (const float*)d_in[6];
    const float* b_out = (const float*)d_in[7];
    float* out = (float*)d_out;

    void *p_Ahi, *p_Alo, *p_Wih_hi, *p_Wih_lo, *p_Wo_hi, *p_Wo_lo;
    void *p_Hhi, *p_Hlo, *p_pre, *p_hs, *p_bsum;
    cudaGetSymbolAddress(&p_Ahi, g_Ahi);       cudaGetSymbolAddress(&p_Alo, g_Alo);
    cudaGetSymbolAddress(&p_Wih_hi, g_Wih_hi); cudaGetSymbolAddress(&p_Wih_lo, g_Wih_lo);
    cudaGetSymbolAddress(&p_Wo_hi, g_Wo_hi);   cudaGetSymbolAddress(&p_Wo_lo, g_Wo_lo);
    cudaGetSymbolAddress(&p_Hhi, g_Hhi);       cudaGetSymbolAddress(&p_Hlo, g_Hlo);
    cudaGetSymbolAddress(&p_pre, g_pre);       cudaGetSymbolAddress(&p_hs, g_hs);
    cudaGetSymbolAddress(&p_bsum, g_bsum);

    cudaFuncSetAttribute(gemm_mma, cudaFuncAttributeMaxDynamicSharedMemorySize, SMEM_B);

    // 1) gather embeddings (split to bf16 hi/lo) + fused bias
    gather_kernel<<<M_ + 1, 256>>>(x, embed, b_ih, b_hh);

    // 2) split weights to bf16 hi/lo
    split_kernel<<<(H_*H_/4 + 255)/256, 256>>>(W_ih,
        (__nv_bfloat16*)p_Wih_hi, (__nv_bfloat16*)p_Wih_lo, (size_t)H_*H_);
    split_kernel<<<(int)(((size_t)V_*H_/4 + 255)/256), 256>>>(W_out,
        (__nv_bfloat16*)p_Wo_hi, (__nv_bfloat16*)p_Wo_lo, (size_t)V_*H_);

    // 3) pre = emb @ W_ih^T + (b_ih + b_hh)   [2048 x 1024]
    gemm_mma<<<dim3(M_/GBM, H_/GBN), 256, SMEM_B>>>(
        (const __nv_bfloat16*)p_Ahi, (const __nv_bfloat16*)p_Alo,
        (const __nv_bfloat16*)p_Wih_hi, (const __nv_bfloat16*)p_Wih_lo,
        (const float*)p_bsum, (float*)p_pre, H_);

    // 4) persistent recurrent scan; writes g_hs and h_final tail of d_out
    scan_kernel<<<SCAN_BLOCKS, SCAN_THREADS>>>(W_hh, out + (size_t)M_ * V_);

    // 5) split hidden states to bf16 hi/lo
    split_kernel<<<(M_*H_/4 + 255)/256, 256>>>((const float*)p_hs,
        (__nv_bfloat16*)p_Hhi, (__nv_bfloat16*)p_Hlo, (size_t)M_*H_);

    // 6) outputs = hs @ W_out^T + b_out   [2048 x 32000]
    gemm_mma<<<dim3(M_/GBM, V_/GBN), 256, SMEM_B>>>(
        (const __nv_bfloat16*)p_Hhi, (const __nv_bfloat16*)p_Hlo,
        (const __nv_bfloat16*)p_Wo_hi, (const __nv_bfloat16*)p_Wo_lo,
        b_out, out, V_);
}

// round 9
// speedup vs baseline: 1.5659x; 1.1392x over previous
#include <cuda_runtime.h>
#include <cuda_bf16.h>
#include <cstdint>

#define B_ 8
#define T_ 256
#define H_ 1024
#define V_ 32000
#define M_ (B_*T_)          // 2048 rows = (b,t)

// ---------------- scratch (device globals; no allocation allowed) ----------
__device__ __align__(16) __nv_bfloat16 g_Ahi[M_*H_];           // emb hi
__device__ __align__(16) __nv_bfloat16 g_Alo[M_*H_];           // emb lo
__device__ __align__(16) __nv_bfloat16 g_Wih_hi[H_*H_];
__device__ __align__(16) __nv_bfloat16 g_Wih_lo[H_*H_];
__device__ __align__(16) __nv_bfloat16 g_Wo_hi[(size_t)V_*H_];
__device__ __align__(16) __nv_bfloat16 g_Wo_lo[(size_t)V_*H_];
__device__ __align__(16) __nv_bfloat16 g_Hhi[M_*H_];           // hs hi
__device__ __align__(16) __nv_bfloat16 g_Hlo[M_*H_];           // hs lo
__device__ __align__(16) float g_pre[M_*H_];   // x_t @ W_ih^T + b_ih + b_hh
__device__ __align__(16) float g_hs [M_*H_];   // hidden states [b][t][j]
__device__ __align__(16) float g_h  [2*B_*H_]; // double-buffered current h
__device__ float g_bsum[H_];
__device__ unsigned g_bar_count;
__device__ unsigned g_bar_gen;

// ---------------- PTX helpers (arch-neutral: ldmatrix/mma/cp.async) --------
__device__ __forceinline__ uint32_t smem_to_u32(const void* p) {
    uint32_t a;
    asm("{ .reg .u64 t; cvta.to.shared.u64 t, %1; cvt.u32.u64 %0, t; }"
        : "=r"(a) : "l"(p));
    return a;
}
__device__ __forceinline__ void ldsm_x4(uint32_t* r, uint32_t addr) {
    asm volatile("ldmatrix.sync.aligned.m8n8.x4.shared.b16 {%0,%1,%2,%3}, [%4];"
        : "=r"(r[0]), "=r"(r[1]), "=r"(r[2]), "=r"(r[3]) : "r"(addr));
}
__device__ __forceinline__ void mma_bf16(float* d, const uint32_t* a, const uint32_t* b) {
    asm volatile(
        "mma.sync.aligned.m16n8k16.row.col.f32.bf16.bf16.f32 "
        "{%0,%1,%2,%3}, {%4,%5,%6,%7}, {%8,%9}, {%0,%1,%2,%3};"
        : "+f"(d[0]), "+f"(d[1]), "+f"(d[2]), "+f"(d[3])
        : "r"(a[0]), "r"(a[1]), "r"(a[2]), "r"(a[3]), "r"(b[0]), "r"(b[1]));
}
__device__ __forceinline__ void cp16(uint32_t saddr, const void* g) {
    asm volatile("cp.async.cg.shared.global [%0], [%1], 16;" :: "r"(saddr), "l"(g));
}
#define CP_COMMIT() asm volatile("cp.async.commit_group;" ::: "memory")
#define CP_WAIT0()  asm volatile("cp.async.wait_group 0;" ::: "memory")
#define CP_WAIT1()  asm volatile("cp.async.wait_group 1;" ::: "memory")

// ---------------- gather: emb rows split to bf16 hi/lo + fused bias --------
__global__ void gather_kernel(const int* __restrict__ x,
                              const float* __restrict__ embed,
                              const float* __restrict__ b_ih,
                              const float* __restrict__ b_hh) {
    int m = blockIdx.x;
    if (m < M_) {
        int tok = x[m];
        for (int i = threadIdx.x; i < H_; i += blockDim.x) {
            float v = embed[(size_t)tok * H_ + i];
            __nv_bfloat16 h = __float2bfloat16(v);
            g_Ahi[(size_t)m * H_ + i] = h;
            g_Alo[(size_t)m * H_ + i] = __float2bfloat16(v - __bfloat162float(h));
        }
    } else {
        for (int i = threadIdx.x; i < H_; i += blockDim.x)
            g_bsum[i] = b_ih[i] + b_hh[i];
    }
}

// ---------------- fp32 -> bf16 hi/lo split ---------------------------------
__global__ void split_kernel(const float* __restrict__ src,
                             __nv_bfloat16* __restrict__ hi,
                             __nv_bfloat16* __restrict__ lo, size_t n) {
    size_t i = ((size_t)blockIdx.x * blockDim.x + threadIdx.x) * 4;
    if (i < n) {
        float4 v = *reinterpret_cast<const float4*>(src + i);
        __nv_bfloat16 h0 = __float2bfloat16(v.x), h1 = __float2bfloat16(v.y);
        __nv_bfloat16 h2 = __float2bfloat16(v.z), h3 = __float2bfloat16(v.w);
        __nv_bfloat162 hh0 = {h0, h1}, hh1 = {h2, h3};
        __nv_bfloat162 ll0 = {__float2bfloat16(v.x - __bfloat162float(h0)),
                              __float2bfloat16(v.y - __bfloat162float(h1))};
        __nv_bfloat162 ll1 = {__float2bfloat16(v.z - __bfloat162float(h2)),
                              __float2bfloat16(v.w - __bfloat162float(h3))};
        *reinterpret_cast<__nv_bfloat162*>(hi + i)     = hh0;
        *reinterpret_cast<__nv_bfloat162*>(hi + i + 2) = hh1;
        *reinterpret_cast<__nv_bfloat162*>(lo + i)     = ll0;
        *reinterpret_cast<__nv_bfloat162*>(lo + i + 2) = ll1;
    }
}

// ---------------- split-bf16 HMMA GEMM (pass-major, chain-free) ------------
// C[r][c] = sum_k A[r][k]*B[c][k] + bias[c] via Ahi*Bhi + Alo*Bhi + Ahi*Blo.
// A: [Mrows][H_] row-major, B: [Ncols][H_] row-major.  K = H_ = 1024 fixed.
#define GBM 128
#define GBN 128
#define GBK 32
#define NKC (H_/GBK)                    // 32 k-chunks
#define LDT 40                          // smem row stride in bf16 (pad 8)
#define MAT_B (GBM*LDT*2)               // 10240 bytes per matrix tile
#define STAGE_B (4*MAT_B)               // 40960 bytes per stage
#define SMEM_B (2*STAGE_B)              // 81920 bytes total

__global__ __launch_bounds__(256, 2)
void gemm_mma(const __nv_bfloat16* __restrict__ Ahi, const __nv_bfloat16* __restrict__ Alo,
              const __nv_bfloat16* __restrict__ Bhi, const __nv_bfloat16* __restrict__ Blo,
              const float* __restrict__ bias, float* __restrict__ C, int Ndim) {
    extern __shared__ __align__(16) char sm[];
    const uint32_t sb = smem_to_u32(sm);
    const int tid  = threadIdx.x;
    const int lane = tid & 31, wid = tid >> 5;
    const int wm = wid & 3, wn = wid >> 2;      // warp tile: rows 32*wm, cols 64*wn
    const int bm = blockIdx.x, bn = blockIdx.y;

    // ---- prefetch chunk c into stage c&1 (8 x cp.async.16B per thread) ----
    auto prefetch = [&](int c) {
        const uint32_t st = sb + (uint32_t)(c & 1) * STAGE_B;
        const int kcol = c * GBK;
        #pragma unroll
        for (int q = 0; q < 2; q++) {
            const int u = tid + 256*q;
            const int r = u >> 2, sg = u & 3;
            const uint32_t so = (uint32_t)(r*LDT + sg*8) * 2;
            const size_t goA = (size_t)(bm*GBM + r) * H_ + kcol + sg*8;
            const size_t goB = (size_t)(bn*GBN + r) * H_ + kcol + sg*8;
            cp16(st + 0*MAT_B + so, Ahi + goA);
            cp16(st + 1*MAT_B + so, Alo + goA);
            cp16(st + 2*MAT_B + so, Bhi + goB);
            cp16(st + 3*MAT_B + so, Blo + goB);
        }
    };

    float acc[2][8][4];
    #pragma unroll
    for (int i = 0; i < 2; i++)
        #pragma unroll
        for (int j = 0; j < 8; j++)
            #pragma unroll
            for (int q = 0; q < 4; q++) acc[i][j][q] = 0.f;

    prefetch(0); CP_COMMIT();

    for (int c = 0; c < NKC; c++) {
        if (c + 1 < NKC) { prefetch(c + 1); CP_COMMIT(); CP_WAIT1(); }
        else             { CP_WAIT0(); }
        __syncthreads();

        const uint32_t st = sb + (uint32_t)(c & 1) * STAGE_B;
        #pragma unroll
        for (int ks = 0; ks < 2; ks++) {
            // A fragments (hi & lo): rows wm*32 + f*16 + lane%16
            uint32_t ah[8], al[8];
            #pragma unroll
            for (int f = 0; f < 2; f++) {
                const int row = wm*32 + f*16 + (lane & 15);
                const uint32_t off = (uint32_t)(row*LDT + ks*16 + (lane >> 4)*8) * 2;
                ldsm_x4(ah + 4*f, st + 0*MAT_B + off);
                ldsm_x4(al + 4*f, st + 1*MAT_B + off);
            }
            // B-fragment smem offsets (shared by hi and lo tiles)
            uint32_t boff[4];
            #pragma unroll
            for (int p = 0; p < 4; p++) {
                const int n  = wn*64 + p*16 + ((lane >> 4) << 3) + (lane & 7);
                const int kc = ks*16 + ((lane >> 3) & 1) * 8;
                boff[p] = (uint32_t)(n*LDT + kc) * 2;
            }
            uint32_t bb[16];
            // ---- load Bhi fragments ----
            #pragma unroll
            for (int p = 0; p < 4; p++) ldsm_x4(bb + 4*p, st + 2*MAT_B + boff[p]);
            // pass 1: Ahi * Bhi  (16 MMAs, all distinct accumulators)
            #pragma unroll
            for (int fm = 0; fm < 2; fm++)
                #pragma unroll
                for (int fn = 0; fn < 8; fn++)
                    mma_bf16(acc[fm][fn], ah + 4*fm, bb + 2*fn);
            // pass 2: Alo * Bhi
            #pragma unroll
            for (int fm = 0; fm < 2; fm++)
                #pragma unroll
                for (int fn = 0; fn < 8; fn++)
                    mma_bf16(acc[fm][fn], al + 4*fm, bb + 2*fn);
            // ---- overwrite with Blo fragments ----
            #pragma unroll
            for (int p = 0; p < 4; p++) ldsm_x4(bb + 4*p, st + 3*MAT_B + boff[p]);
            // pass 3: Ahi * Blo
            #pragma unroll
            for (int fm = 0; fm < 2; fm++)
                #pragma unroll
                for (int fn = 0; fn < 8; fn++)
                    mma_bf16(acc[fm][fn], ah + 4*fm, bb + 2*fn);
        }
        __syncthreads();
    }

    // ---- epilogue: acc + bias -> C ----
    #pragma unroll
    for (int fm = 0; fm < 2; fm++) {
        const int row = bm*GBM + wm*32 + fm*16 + (lane >> 2);
        #pragma unroll
        for (int fn = 0; fn < 8; fn++) {
            const int col = bn*GBN + wn*64 + fn*8 + (lane & 3)*2;
            const float2 bv = *reinterpret_cast<const float2*>(bias + col);
            float2 o0, o1;
            o0.x = acc[fm][fn][0] + bv.x; o0.y = acc[fm][fn][1] + bv.y;
            o1.x = acc[fm][fn][2] + bv.x; o1.y = acc[fm][fn][3] + bv.y;
            *reinterpret_cast<float2*>(C + (size_t)row     * Ndim + col) = o0;
            *reinterpret_cast<float2*>(C + (size_t)(row+8) * Ndim + col) = o1;
        }
    }
}

// ---------------- persistent scan kernel (R6 config: 128 x 256) ------------
#define SCAN_BLOCKS 128

__device__ __forceinline__ void grid_barrier(int nb) {
    __syncthreads();
    if (threadIdx.x == 0) {
        unsigned g = *((volatile unsigned*)&g_bar_gen);
        __threadfence();
        if (atomicAdd(&g_bar_count, 1) == (unsigned)(nb - 1)) {
            g_bar_count = 0;
            __threadfence();
            *((volatile unsigned*)&g_bar_gen) = g + 1;
        } else {
            while (*((volatile unsigned*)&g_bar_gen) == g) { __nanosleep(32); }
        }
        __threadfence();
    }
    __syncthreads();
}

__global__ __launch_bounds__(256)
void scan_kernel(const float* __restrict__ Whh, float* __restrict__ hfinal) {
    __shared__ __align__(16) float hsh[B_*H_];   // 32 KB
    const int tid  = threadIdx.x;
    const int warp = tid >> 5;
    const int lane = tid & 31;
    const int j    = blockIdx.x * 8 + warp;      // one output column per warp

    float4 w[8];
    const float4* wrow = reinterpret_cast<const float4*>(Whh + (size_t)j * H_);
    #pragma unroll
    for (int i = 0; i < 8; i++) w[i] = wrow[lane + 32*i];

    for (int idx = blockIdx.x*256 + tid; idx < B_*H_; idx += SCAN_BLOCKS*256)
        g_h[idx] = 0.f;
    grid_barrier(SCAN_BLOCKS);

    for (int t = 0; t < T_; t++) {
        const int rp = t & 1, wp = rp ^ 1;
        float4* hs4 = reinterpret_cast<float4*>(hsh);
        const float4* hg4 = reinterpret_cast<const float4*>(g_h + rp*B_*H_);
        #pragma unroll
        for (int i = 0; i < (B_*H_/4)/256; i++) hs4[tid + 256*i] = hg4[tid + 256*i];
        __syncthreads();

        float acc[B_];
        #pragma unroll
        for (int b = 0; b < B_; b++) acc[b] = 0.f;
        #pragma unroll
        for (int i = 0; i < 8; i++) {
            const float4 wv = w[i];
            #pragma unroll
            for (int b = 0; b < B_; b++) {
                const float4 hv = *reinterpret_cast<const float4*>(&hsh[b*H_ + lane*4 + 128*i]);
                acc[b] += wv.x*hv.x + wv.y*hv.y + wv.z*hv.z + wv.w*hv.w;
            }
        }
        #pragma unroll
        for (int b = 0; b < B_; b++) {
            #pragma unroll
            for (int off = 16; off; off >>= 1)
                acc[b] += __shfl_xor_sync(0xffffffffu, acc[b], off);
        }
        if (lane < B_) {
            float a = acc[0];
            if (lane == 1) a = acc[1];
            if (lane == 2) a = acc[2];
            if (lane == 3) a = acc[3];
            if (lane == 4) a = acc[4];
            if (lane == 5) a = acc[5];
            if (lane == 6) a = acc[6];
            if (lane == 7) a = acc[7];
            const float hn = tanhf(a + g_pre[(size_t)lane*(T_*H_) + t*H_ + j]);
            g_h[wp*B_*H_ + lane*H_ + j] = hn;
            g_hs[(size_t)lane*(T_*H_) + t*H_ + j] = hn;
            if (t == T_-1) hfinal[lane*H_ + j] = hn;
        }
        __threadfence();
        grid_barrier(SCAN_BLOCKS);
    }
}

// ---------------- launch ----------------------------------------------------
extern "C" void kernel_launch(void* const* d_in, const int* in_sizes, int n_in,
                              void* d_out, int out_size) {
    const int*   x     = (const int*)  d_in[0];
    const float* embed = (const float*)d_in[1];
    const float* W_ih  = (const float*)d_in[2];
    const float* b_ih  = (const float*)d_in[3];
    const float* W_hh  = (const float*)d_in[4];
    const float* b_hh  = (const float*)d_in[5];
    const float* W_out = (const float*)d_in[6];
    const float* b_out = (const float*)d_in[7];
    float* out = (float*)d_out;

    void *p_Ahi, *p_Alo, *p_Wih_hi, *p_Wih_lo, *p_Wo_hi, *p_Wo_lo;
    void *p_Hhi, *p_Hlo, *p_pre, *p_hs, *p_bsum;
    cudaGetSymbolAddress(&p_Ahi, g_Ahi);       cudaGetSymbolAddress(&p_Alo, g_Alo);
    cudaGetSymbolAddress(&p_Wih_hi, g_Wih_hi); cudaGetSymbolAddress(&p_Wih_lo, g_Wih_lo);
    cudaGetSymbolAddress(&p_Wo_hi, g_Wo_hi);   cudaGetSymbolAddress(&p_Wo_lo, g_Wo_lo);
    cudaGetSymbolAddress(&p_Hhi, g_Hhi);       cudaGetSymbolAddress(&p_Hlo, g_Hlo);
    cudaGetSymbolAddress(&p_pre, g_pre);       cudaGetSymbolAddress(&p_hs, g_hs);
    cudaGetSymbolAddress(&p_bsum, g_bsum);

    cudaFuncSetAttribute(gemm_mma, cudaFuncAttributeMaxDynamicSharedMemorySize, SMEM_B);

    // 1) gather embeddings (split to bf16 hi/lo) + fused bias
    gather_kernel<<<M_ + 1, 256>>>(x, embed, b_ih, b_hh);

    // 2) split weights to bf16 hi/lo
    split_kernel<<<(H_*H_/4 + 255)/256, 256>>>(W_ih,
        (__nv_bfloat16*)p_Wih_hi, (__nv_bfloat16*)p_Wih_lo, (size_t)H_*H_);
    split_kernel<<<(int)(((size_t)V_*H_/4 + 255)/256), 256>>>(W_out,
        (__nv_bfloat16*)p_Wo_hi, (__nv_bfloat16*)p_Wo_lo, (size_t)V_*H_);

    // 3) pre = emb @ W_ih^T + (b_ih + b_hh)   [2048 x 1024]
    gemm_mma<<<dim3(M_/GBM, H_/GBN), 256, SMEM_B>>>(
        (const __nv_bfloat16*)p_Ahi, (const __nv_bfloat16*)p_Alo,
        (const __nv_bfloat16*)p_Wih_hi, (const __nv_bfloat16*)p_Wih_lo,
        (const float*)p_bsum, (float*)p_pre, H_);

    // 4) persistent recurrent scan; writes g_hs and h_final tail of d_out
    scan_kernel<<<SCAN_BLOCKS, 256>>>(W_hh, out + (size_t)M_ * V_);

    // 5) split hidden states to bf16 hi/lo
    split_kernel<<<(M_*H_/4 + 255)/256, 256>>>((const float*)p_hs,
        (__nv_bfloat16*)p_Hhi, (__nv_bfloat16*)p_Hlo, (size_t)M_*H_);

    // 6) outputs = hs @ W_out^T + b_out   [2048 x 32000]
    gemm_mma<<<dim3(M_/GBM, V_/GBN), 256, SMEM_B>>>(
        (const __nv_bfloat16*)p_Hhi, (const __nv_bfloat16*)p_Hlo,
        (const __nv_bfloat16*)p_Wo_hi, (const __nv_bfloat16*)p_Wo_lo,
        b_out, out, V_);
}